// round 5
// baseline (speedup 1.0000x reference)
#include <cuda_runtime.h>

#define H 51
#define BB 16
#define NROWS 459        // 153 whh1 + 153 whh2 + 153 wih2
#define NDOT 918         // 2 threads per row (k-split)
#define NTHREADS 1024
#define KHALF 28         // k's per half-thread (pad 51 -> 56)
#define HPK 56           // padded k extent of h buffers
#define HSTRIDE (HPK*16) // floats per h buffer [56][16]
#define GPU 9            // gbuf pitch (ull)
#define GPF 18           // gbuf pitch (floats)
#define NPW 816          // pointwise tasks per layer

typedef unsigned long long ull;

#define FFMA2(d, a, b_) asm("fma.rn.f32x2 %0, %1, %2, %0;" : "+l"(d) : "l"(a), "l"(b_))
#define ADDF2(d, a)     asm("add.rn.f32x2 %0, %0, %1;"     : "+l"(d) : "l"(a))

__device__ __forceinline__ ull pack2(float lo, float hi) {
    ull r;
    asm("mov.b64 %0, {%1,%2};" : "=l"(r) : "f"(lo), "f"(hi));
    return r;
}
__device__ __forceinline__ float sigf(float v) {
    return __fdividef(1.0f, 1.0f + __expf(-v));
}
__device__ __forceinline__ float tanh_f(float v) {
    return 1.0f - __fdividef(2.0f, __expf(2.0f * v) + 1.0f);
}

__global__ __launch_bounds__(NTHREADS, 1)
void gru2_kernel(const float* __restrict__ input,
                 const float* __restrict__ w_ih1, const float* __restrict__ w_hh1,
                 const float* __restrict__ b_ih1, const float* __restrict__ b_hh1,
                 const float* __restrict__ w_ih2, const float* __restrict__ w_hh2,
                 const float* __restrict__ b_ih2, const float* __restrict__ b_hh2,
                 const float* __restrict__ w_lin, const float* __restrict__ b_lin,
                 float* __restrict__ out, int T, int F)
{
    extern __shared__ float sm[];
    float* hT1   = sm;                         // [2][56][16]  h1, k-major
    float* hT2   = hT1 + 2 * HSTRIDE;          // [2][56][16]  h2
    ull*   gbufU = (ull*)(sm + 4 * HSTRIDE);   // [459][9]
    float* gbufF = (float*)gbufU;
    float* tabs  = (float*)(gbufU + NROWS * GPU);  // w1r|w1z|w1n|c1r|c1z|c1n|wl
    float* xbuf  = tabs + 7 * H;               // [16]
    float* oacc  = xbuf + BB;                  // [2][16]

    const int tid = threadIdx.x;
    const int gb0 = blockIdx.x * BB;
    const int TOT = T + F;

    for (int i = tid; i < 4 * HSTRIDE; i += NTHREADS) sm[i] = 0.f;
    if (tid < H) {
        tabs[tid]         = __ldg(&w_ih1[tid]);
        tabs[H + tid]     = __ldg(&w_ih1[H + tid]);
        tabs[2 * H + tid] = __ldg(&w_ih1[2 * H + tid]);
        tabs[3 * H + tid] = __ldg(&b_ih1[tid]);
        tabs[4 * H + tid] = __ldg(&b_ih1[H + tid]);
        tabs[5 * H + tid] = __ldg(&b_ih1[2 * H + tid]);
        tabs[6 * H + tid] = __ldg(&w_lin[tid]);
    }
    if (tid < 2 * BB) oacc[tid] = 0.f;

    // Row assignment: p = row (0..458), half = k-range (0: k<28, 1: k>=28)
    const int p    = tid >> 1;
    const int half = tid & 1;
    const unsigned pmask = 0x3u << (tid & 30);

    const float* wsrc = w_hh1;
    float b0 = 0.f;
    int hsel = 0;
    if (p < 153)      { wsrc = w_hh1 + p * H;         b0 = __ldg(&b_hh1[p]);       hsel = 0; }
    else if (p < 306) { wsrc = w_hh2 + (p - 153) * H; b0 = __ldg(&b_hh2[p - 153]); hsel = 1; }
    else              { wsrc = w_ih2 + (p - 306) * H; b0 = __ldg(&b_ih2[p - 306]); hsel = 0; }

    float w[KHALF];
    #pragma unroll
    for (int j = 0; j < KHALF; ++j) {
        int k = half * KHALF + j;
        w[j] = (k < H) ? __ldg(&wsrc[k]) : 0.f;
    }
    const ull bias2 = half ? 0ULL : pack2(b0, b0);
    const float blin = __ldg(&b_lin[0]);
    const int pxor = hsel ? 0 : 1;
    const float* hbase = hsel ? hT2 : hT1;
    const int hoff = half * (KHALF * 16);

    __syncthreads();

    for (int i = 0; i <= TOT; ++i) {
        const int par = i & 1;

        // ================= DOT STAGE =================
        if (tid < NDOT) {
            const float* hp = hbase + ((par ^ pxor) * HSTRIDE) + hoff;
            ull acc[8];
            #pragma unroll
            for (int bp = 0; bp < 8; ++bp) acc[bp] = bias2;
            #pragma unroll
            for (int k = 0; k < KHALF; ++k) {
                const ull wd = pack2(w[k], w[k]);
                const ulonglong2* q = (const ulonglong2*)(hp + k * 16);
                ulonglong2 q0 = q[0], q1 = q[1], q2 = q[2], q3 = q[3];
                FFMA2(acc[0], wd, q0.x); FFMA2(acc[1], wd, q0.y);
                FFMA2(acc[2], wd, q1.x); FFMA2(acc[3], wd, q1.y);
                FFMA2(acc[4], wd, q2.x); FFMA2(acc[5], wd, q2.y);
                FFMA2(acc[6], wd, q3.x); FFMA2(acc[7], wd, q3.y);
            }
            #pragma unroll
            for (int bp = 0; bp < 8; ++bp) {
                ull o = __shfl_xor_sync(pmask, acc[bp], 1);
                ADDF2(acc[bp], o);
            }
            if (!half) {
                ull* go = gbufU + p * GPU;
                #pragma unroll
                for (int bp = 0; bp < 8; ++bp) go[bp] = acc[bp];
            }
        } else {
            int j = tid - NDOT;
            if (j < BB) {
                if (i >= 2) out[(size_t)(gb0 + j) * TOT + (i - 2)] = oacc[((i - 1) & 1) * BB + j] + blin;
                oacc[par * BB + j] = 0.f;
                if (i < T) xbuf[j] = __ldg(&input[(size_t)(gb0 + j) * T + i]);
            }
        }
        __syncthreads();

        // ================= POINTWISE STAGE =================
        float* oa  = oacc + par * BB;
        float* h2c = hT2 + par * HSTRIDE;          // h2[i-2]
        float* h2n = hT2 + (par ^ 1) * HSTRIDE;    // h2[i-1]
        float* h1c = hT1 + (par ^ 1) * HSTRIDE;    // h1[i-1]
        float* h1n = hT1 + par * HSTRIDE;          // h1[i]

        if (i < T) {
            for (int j = tid; j < 2 * NPW; j += NTHREADS) {
                if (j < NPW) {
                    if (i > 0) {
                        int u = j >> 4, b = j & 15;
                        float dir = gbufF[(306 + u) * GPF + b];
                        float diz = gbufF[(357 + u) * GPF + b];
                        float din = gbufF[(408 + u) * GPF + b];
                        float d2r = gbufF[(153 + u) * GPF + b];
                        float d2z = gbufF[(204 + u) * GPF + b];
                        float d2n = gbufF[(255 + u) * GPF + b];
                        float r = sigf(dir + d2r);
                        float z = sigf(diz + d2z);
                        float n = tanh_f(fmaf(r, d2n, din));
                        float hold = h2c[u * 16 + b];
                        float hnew = n + z * (hold - n);
                        h2n[u * 16 + b] = hnew;
                        atomicAdd(&oa[b], tabs[6 * H + u] * hnew);
                    }
                } else {
                    int jj = j - NPW;
                    int u = jj >> 4, b = jj & 15;
                    float x = xbuf[b];
                    float ar = gbufF[u * GPF + b];
                    float az = gbufF[(51 + u) * GPF + b];
                    float an = gbufF[(102 + u) * GPF + b];
                    float r = sigf(fmaf(x, tabs[u], tabs[3 * H + u]) + ar);
                    float z = sigf(fmaf(x, tabs[H + u], tabs[4 * H + u]) + az);
                    float n = tanh_f(fmaf(x, tabs[2 * H + u], tabs[5 * H + u]) + r * an);
                    float hold = h1c[u * 16 + b];
                    h1n[u * 16 + b] = n + z * (hold - n);
                }
            }
            __syncthreads();
        } else {
            for (int j = tid; j < NPW; j += NTHREADS) {
                int u = j >> 4, b = j & 15;
                float dir = gbufF[(306 + u) * GPF + b];
                float diz = gbufF[(357 + u) * GPF + b];
                float din = gbufF[(408 + u) * GPF + b];
                float d2r = gbufF[(153 + u) * GPF + b];
                float d2z = gbufF[(204 + u) * GPF + b];
                float d2n = gbufF[(255 + u) * GPF + b];
                float r = sigf(dir + d2r);
                float z = sigf(diz + d2z);
                float n = tanh_f(fmaf(r, d2n, din));
                float hold = h2c[u * 16 + b];
                float hnew = n + z * (hold - n);
                h2n[u * 16 + b] = hnew;
                atomicAdd(&oa[b], tabs[6 * H + u] * hnew);
            }
            __syncthreads();
            for (int j = tid; j < NPW; j += NTHREADS) {
                int u = j >> 4, b = j & 15;
                float x = oa[b] + blin;
                float ar = gbufF[u * GPF + b];
                float az = gbufF[(51 + u) * GPF + b];
                float an = gbufF[(102 + u) * GPF + b];
                float r = sigf(fmaf(x, tabs[u], tabs[3 * H + u]) + ar);
                float z = sigf(fmaf(x, tabs[H + u], tabs[4 * H + u]) + az);
                float n = tanh_f(fmaf(x, tabs[2 * H + u], tabs[5 * H + u]) + r * an);
                float hold = h1c[u * 16 + b];
                h1n[u * 16 + b] = n + z * (hold - n);
            }
            __syncthreads();
        }
    }

    if (tid < BB)
        out[(size_t)(gb0 + tid) * TOT + (TOT - 1)] = oacc[(TOT & 1) * BB + tid] + blin;
}

extern "C" void kernel_launch(void* const* d_in, const int* in_sizes, int n_in,
                              void* d_out, int out_size) {
    const float* input = (const float*)d_in[0];
    const float* w_ih1 = (const float*)d_in[2];
    const float* w_hh1 = (const float*)d_in[3];
    const float* b_ih1 = (const float*)d_in[4];
    const float* b_hh1 = (const float*)d_in[5];
    const float* w_ih2 = (const float*)d_in[6];
    const float* w_hh2 = (const float*)d_in[7];
    const float* b_ih2 = (const float*)d_in[8];
    const float* b_hh2 = (const float*)d_in[9];
    const float* w_lin = (const float*)d_in[10];
    const float* b_lin = (const float*)d_in[11];

    const int B   = 2048;
    const int T   = in_sizes[0] / B;
    const int TOT = out_size / B;
    const int F   = TOT - T;

    size_t smem = (size_t)(4 * HSTRIDE * 4 + NROWS * GPU * 8 + (7 * H + BB + 2 * BB) * 4);
    cudaFuncSetAttribute(gru2_kernel, cudaFuncAttributeMaxDynamicSharedMemorySize, (int)smem);

    gru2_kernel<<<B / BB, NTHREADS, smem>>>(
        input, w_ih1, w_hh1, b_ih1, b_hh1,
        w_ih2, w_hh2, b_ih2, b_hh2,
        w_lin, b_lin, (float*)d_out, T, F);
}

// round 6
// speedup vs baseline: 1.6121x; 1.6121x over previous
#include <cuda_runtime.h>

#define H 51
#define BB 16
#define NROWS 459        // 153 whh1 + 153 whh2 + 153 wih2
#define NDOT 918         // 2 threads per row (k-split)
#define NTHREADS 1024
#define KHALF 26         // k's per half-thread (pad 51 -> 52)
#define HOFF 424         // float offset of half-1 k-range: 26*16 + 8 (gap) -> 1696B ≡ 32 mod 128
#define HSTRIDE 840      // floats per h buffer: 52*16 + 8 gap
#define GPU 9            // gbuf pitch (ull)
#define GPF 18           // gbuf pitch (floats)
#define NPW 816          // pointwise tasks per layer

typedef unsigned long long ull;

#define FFMA2(d, a, b_) asm("fma.rn.f32x2 %0, %1, %2, %0;" : "+l"(d) : "l"(a), "l"(b_))
#define ADDF2(d, a)     asm("add.rn.f32x2 %0, %0, %1;"     : "+l"(d) : "l"(a))

__device__ __forceinline__ ull pack2(float lo, float hi) {
    ull r;
    asm("mov.b64 %0, {%1,%2};" : "=l"(r) : "f"(lo), "f"(hi));
    return r;
}
__device__ __forceinline__ float sigf(float v) {
    return __fdividef(1.0f, 1.0f + __expf(-v));
}
__device__ __forceinline__ float tanh_f(float v) {
    return 1.0f - __fdividef(2.0f, __expf(2.0f * v) + 1.0f);
}
// h element index with mid-gap: k<26 -> k*16, k>=26 -> k*16 + 8
__device__ __forceinline__ int hidx(int k) { return k * 16 + (k >= KHALF ? 8 : 0); }

__global__ __launch_bounds__(NTHREADS, 1)
void gru2_kernel(const float* __restrict__ input,
                 const float* __restrict__ w_ih1, const float* __restrict__ w_hh1,
                 const float* __restrict__ b_ih1, const float* __restrict__ b_hh1,
                 const float* __restrict__ w_ih2, const float* __restrict__ w_hh2,
                 const float* __restrict__ b_ih2, const float* __restrict__ b_hh2,
                 const float* __restrict__ w_lin, const float* __restrict__ b_lin,
                 float* __restrict__ out, int T, int F)
{
    extern __shared__ float sm[];
    float* hT1   = sm;                         // [2][HSTRIDE]  h1, k-major + gap
    float* hT2   = hT1 + 2 * HSTRIDE;          // [2][HSTRIDE]  h2
    ull*   gbufU = (ull*)(sm + 4 * HSTRIDE);   // [459][9]
    float* gbufF = (float*)gbufU;
    float* tabs  = (float*)(gbufU + NROWS * GPU);  // w1r|w1z|w1n|c1r|c1z|c1n|wl
    float* xbuf  = tabs + 7 * H;               // [16]
    float* oacc  = xbuf + BB;                  // [2][16]

    const int tid = threadIdx.x;
    const int gb0 = blockIdx.x * BB;
    const int TOT = T + F;

    for (int i = tid; i < 4 * HSTRIDE; i += NTHREADS) sm[i] = 0.f;
    if (tid < H) {
        tabs[tid]         = __ldg(&w_ih1[tid]);
        tabs[H + tid]     = __ldg(&w_ih1[H + tid]);
        tabs[2 * H + tid] = __ldg(&w_ih1[2 * H + tid]);
        tabs[3 * H + tid] = __ldg(&b_ih1[tid]);
        tabs[4 * H + tid] = __ldg(&b_ih1[H + tid]);
        tabs[5 * H + tid] = __ldg(&b_ih1[2 * H + tid]);
        tabs[6 * H + tid] = __ldg(&w_lin[tid]);
    }
    if (tid < 2 * BB) oacc[tid] = 0.f;

    // Row assignment: p = row (0..458), half = k-range (0: k<26, 1: k>=26)
    const int p    = tid >> 1;
    const int half = tid & 1;
    const unsigned pmask = 0x3u << (tid & 30);

    const float* wsrc = w_hh1;
    float b0 = 0.f;
    int hsel = 0;
    if (p < 153)      { wsrc = w_hh1 + p * H;         b0 = __ldg(&b_hh1[p]);       hsel = 0; }
    else if (p < 306) { wsrc = w_hh2 + (p - 153) * H; b0 = __ldg(&b_hh2[p - 153]); hsel = 1; }
    else              { wsrc = w_ih2 + (p - 306) * H; b0 = __ldg(&b_ih2[p - 306]); hsel = 0; }

    float w[KHALF];
    #pragma unroll
    for (int j = 0; j < KHALF; ++j) {
        int k = half * KHALF + j;
        w[j] = (k < H) ? __ldg(&wsrc[k]) : 0.f;
    }
    const ull bias2 = half ? 0ULL : pack2(b0, b0);
    const float blin = __ldg(&b_lin[0]);
    const int pxor = hsel ? 0 : 1;
    const float* hbase = hsel ? hT2 : hT1;
    const int hoff = half * HOFF;

    __syncthreads();

    for (int i = 0; i <= TOT; ++i) {
        const int par = i & 1;

        // ================= DOT STAGE =================
        if (tid < NDOT) {
            const float* hp = hbase + ((par ^ pxor) * HSTRIDE) + hoff;
            ull acc[8];
            #pragma unroll
            for (int bp = 0; bp < 8; ++bp) acc[bp] = bias2;
            #pragma unroll
            for (int k = 0; k < KHALF; ++k) {
                const ull wd = pack2(w[k], w[k]);
                const ulonglong2* q = (const ulonglong2*)(hp + k * 16);
                ulonglong2 q0 = q[0], q1 = q[1], q2 = q[2], q3 = q[3];
                FFMA2(acc[0], wd, q0.x); FFMA2(acc[1], wd, q0.y);
                FFMA2(acc[2], wd, q1.x); FFMA2(acc[3], wd, q1.y);
                FFMA2(acc[4], wd, q2.x); FFMA2(acc[5], wd, q2.y);
                FFMA2(acc[6], wd, q3.x); FFMA2(acc[7], wd, q3.y);
            }
            #pragma unroll
            for (int bp = 0; bp < 8; ++bp) {
                ull o = __shfl_xor_sync(pmask, acc[bp], 1);
                ADDF2(acc[bp], o);
            }
            if (!half) {
                ull* go = gbufU + p * GPU;
                #pragma unroll
                for (int bp = 0; bp < 8; ++bp) go[bp] = acc[bp];
            }
        } else {
            int j = tid - NDOT;
            if (j < BB) {
                if (i >= 2) out[(size_t)(gb0 + j) * TOT + (i - 2)] = oacc[((i - 1) & 1) * BB + j] + blin;
                oacc[par * BB + j] = 0.f;
                if (i < T) xbuf[j] = __ldg(&input[(size_t)(gb0 + j) * T + i]);
            }
        }
        __syncthreads();

        // ================= POINTWISE STAGE =================
        float* oa  = oacc + par * BB;
        float* h2c = hT2 + par * HSTRIDE;          // h2[i-2]
        float* h2n = hT2 + (par ^ 1) * HSTRIDE;    // h2[i-1]
        float* h1c = hT1 + (par ^ 1) * HSTRIDE;    // h1[i-1]
        float* h1n = hT1 + par * HSTRIDE;          // h1[i]

        if (i < T) {
            for (int j = tid; j < 2 * NPW; j += NTHREADS) {
                if (j < NPW) {
                    if (i > 0) {
                        int u = j >> 4, b = j & 15;
                        int hx = hidx(u) + b;
                        float dir = gbufF[(306 + u) * GPF + b];
                        float diz = gbufF[(357 + u) * GPF + b];
                        float din = gbufF[(408 + u) * GPF + b];
                        float d2r = gbufF[(153 + u) * GPF + b];
                        float d2z = gbufF[(204 + u) * GPF + b];
                        float d2n = gbufF[(255 + u) * GPF + b];
                        float r = sigf(dir + d2r);
                        float z = sigf(diz + d2z);
                        float n = tanh_f(fmaf(r, d2n, din));
                        float hold = h2c[hx];
                        float hnew = n + z * (hold - n);
                        h2n[hx] = hnew;
                        atomicAdd(&oa[b], tabs[6 * H + u] * hnew);
                    }
                } else {
                    int jj = j - NPW;
                    int u = jj >> 4, b = jj & 15;
                    int hx = hidx(u) + b;
                    float x = xbuf[b];
                    float ar = gbufF[u * GPF + b];
                    float az = gbufF[(51 + u) * GPF + b];
                    float an = gbufF[(102 + u) * GPF + b];
                    float r = sigf(fmaf(x, tabs[u], tabs[3 * H + u]) + ar);
                    float z = sigf(fmaf(x, tabs[H + u], tabs[4 * H + u]) + az);
                    float n = tanh_f(fmaf(x, tabs[2 * H + u], tabs[5 * H + u]) + r * an);
                    float hold = h1c[hx];
                    h1n[hx] = n + z * (hold - n);
                }
            }
            __syncthreads();
        } else {
            for (int j = tid; j < NPW; j += NTHREADS) {
                int u = j >> 4, b = j & 15;
                int hx = hidx(u) + b;
                float dir = gbufF[(306 + u) * GPF + b];
                float diz = gbufF[(357 + u) * GPF + b];
                float din = gbufF[(408 + u) * GPF + b];
                float d2r = gbufF[(153 + u) * GPF + b];
                float d2z = gbufF[(204 + u) * GPF + b];
                float d2n = gbufF[(255 + u) * GPF + b];
                float r = sigf(dir + d2r);
                float z = sigf(diz + d2z);
                float n = tanh_f(fmaf(r, d2n, din));
                float hold = h2c[hx];
                float hnew = n + z * (hold - n);
                h2n[hx] = hnew;
                atomicAdd(&oa[b], tabs[6 * H + u] * hnew);
            }
            __syncthreads();
            for (int j = tid; j < NPW; j += NTHREADS) {
                int u = j >> 4, b = j & 15;
                int hx = hidx(u) + b;
                float x = oa[b] + blin;
                float ar = gbufF[u * GPF + b];
                float az = gbufF[(51 + u) * GPF + b];
                float an = gbufF[(102 + u) * GPF + b];
                float r = sigf(fmaf(x, tabs[u], tabs[3 * H + u]) + ar);
                float z = sigf(fmaf(x, tabs[H + u], tabs[4 * H + u]) + az);
                float n = tanh_f(fmaf(x, tabs[2 * H + u], tabs[5 * H + u]) + r * an);
                float hold = h1c[hx];
                h1n[hx] = n + z * (hold - n);
            }
            __syncthreads();
        }
    }

    if (tid < BB)
        out[(size_t)(gb0 + tid) * TOT + (TOT - 1)] = oacc[(TOT & 1) * BB + tid] + blin;
}

extern "C" void kernel_launch(void* const* d_in, const int* in_sizes, int n_in,
                              void* d_out, int out_size) {
    const float* input = (const float*)d_in[0];
    const float* w_ih1 = (const float*)d_in[2];
    const float* w_hh1 = (const float*)d_in[3];
    const float* b_ih1 = (const float*)d_in[4];
    const float* b_hh1 = (const float*)d_in[5];
    const float* w_ih2 = (const float*)d_in[6];
    const float* w_hh2 = (const float*)d_in[7];
    const float* b_ih2 = (const float*)d_in[8];
    const float* b_hh2 = (const float*)d_in[9];
    const float* w_lin = (const float*)d_in[10];
    const float* b_lin = (const float*)d_in[11];

    const int B   = 2048;
    const int T   = in_sizes[0] / B;
    const int TOT = out_size / B;
    const int F   = TOT - T;

    size_t smem = (size_t)(4 * HSTRIDE * 4 + NROWS * GPU * 8 + (7 * H + BB + 2 * BB) * 4);
    cudaFuncSetAttribute(gru2_kernel, cudaFuncAttributeMaxDynamicSharedMemorySize, (int)smem);

    gru2_kernel<<<B / BB, NTHREADS, smem>>>(
        input, w_ih1, w_hh1, b_ih1, b_hh1,
        w_ih2, w_hh2, b_ih2, b_hh2,
        w_lin, b_lin, (float*)d_out, T, F);
}

// round 7
// speedup vs baseline: 2.1059x; 1.3063x over previous
#include <cuda_runtime.h>

#define H 51
#define BB 16
#define NTHREADS 512
#define NPAIRS 231       // 3 regions x 77 row-pairs (regions padded 153->154)
#define NDOT 462         // 2 threads per pair (k-split)
#define KHALF 26         // k's per half (pad 51 -> 52)
#define HOFF 424         // half-1 k-range float offset: 26*16 + 8 -> 1696B ≡ 32 mod 128
#define HSTRIDE 840      // floats per h buffer: 52*16 + 8 gap
#define GROWS 462        // gbuf rows: 3 regions x 154
#define GPU 9            // gbuf pitch (ull)
#define GPF 18           // gbuf pitch (floats)
#define GR2 154
#define GR3 308
#define NPW 816          // pointwise tasks per layer

typedef unsigned long long ull;

#define FFMA2(d, a, b_) asm("fma.rn.f32x2 %0, %1, %2, %0;" : "+l"(d) : "l"(a), "l"(b_))
#define ADDF2(d, a)     asm("add.rn.f32x2 %0, %0, %1;"     : "+l"(d) : "l"(a))

__device__ __forceinline__ ull pack2(float lo, float hi) {
    ull r;
    asm("mov.b64 %0, {%1,%2};" : "=l"(r) : "f"(lo), "f"(hi));
    return r;
}
__device__ __forceinline__ float sigf(float v) {
    return __fdividef(1.0f, 1.0f + __expf(-v));
}
__device__ __forceinline__ float tanh_f(float v) {
    return 1.0f - __fdividef(2.0f, __expf(2.0f * v) + 1.0f);
}
// h element index with mid-gap: k<26 -> k*16, k>=26 -> k*16 + 8
__device__ __forceinline__ int hidx(int k) { return k * 16 + (k >= KHALF ? 8 : 0); }

__global__ __launch_bounds__(NTHREADS, 1)
void gru2_kernel(const float* __restrict__ input,
                 const float* __restrict__ w_ih1, const float* __restrict__ w_hh1,
                 const float* __restrict__ b_ih1, const float* __restrict__ b_hh1,
                 const float* __restrict__ w_ih2, const float* __restrict__ w_hh2,
                 const float* __restrict__ b_ih2, const float* __restrict__ b_hh2,
                 const float* __restrict__ w_lin, const float* __restrict__ b_lin,
                 float* __restrict__ out, int T, int F)
{
    extern __shared__ float sm[];
    float* hT1   = sm;                         // [2][HSTRIDE]  h1, k-major + gap
    float* hT2   = hT1 + 2 * HSTRIDE;          // [2][HSTRIDE]  h2
    ull*   gbufU = (ull*)(sm + 4 * HSTRIDE);   // [462][9]
    float* gbufF = (float*)gbufU;
    float* tabs  = (float*)(gbufU + GROWS * GPU);  // w1r|w1z|w1n|c1r|c1z|c1n|wl
    float* xbuf  = tabs + 7 * H;               // [16]
    float* oacc  = xbuf + BB;                  // [2][16]

    const int tid = threadIdx.x;
    const int gb0 = blockIdx.x * BB;
    const int TOT = T + F;

    for (int i = tid; i < 4 * HSTRIDE; i += NTHREADS) sm[i] = 0.f;
    if (tid < H) {
        tabs[tid]         = __ldg(&w_ih1[tid]);
        tabs[H + tid]     = __ldg(&w_ih1[H + tid]);
        tabs[2 * H + tid] = __ldg(&w_ih1[2 * H + tid]);
        tabs[3 * H + tid] = __ldg(&b_ih1[tid]);
        tabs[4 * H + tid] = __ldg(&b_ih1[H + tid]);
        tabs[5 * H + tid] = __ldg(&b_ih1[2 * H + tid]);
        tabs[6 * H + tid] = __ldg(&w_lin[tid]);
    }
    if (tid < 2 * BB) oacc[tid] = 0.f;

    // Thread map: P = pair id (0..230), half = k-range half.
    // region = P/77 (0: whh1 x h1, 1: whh2 x h2, 2: wih2 x h1)
    // rows within region: ra = 2q, rb = 2q+1 (153 = padded dummy)
    const bool comp = (tid < NDOT);
    const int P    = comp ? (tid >> 1) : 0;
    const int half = tid & 1;
    const unsigned pmask = 0x3u << (tid & 30);

    const int region = P / 77;
    const int q      = P - region * 77;
    const int ra = 2 * q, rb = 2 * q + 1;
    const bool vB = (rb < 153);
    const float* base = (region == 0) ? w_hh1 : ((region == 1) ? w_hh2 : w_ih2);
    const float* bsrc = (region == 0) ? b_hh1 : ((region == 1) ? b_hh2 : b_ih2);
    const int hsel = (region == 1);

    float wA[KHALF], wB[KHALF];
    #pragma unroll
    for (int j = 0; j < KHALF; ++j) {
        int k = half * KHALF + j;
        wA[j] = (comp && k < H) ? __ldg(&base[ra * H + k]) : 0.f;
        wB[j] = (comp && vB && k < H) ? __ldg(&base[rb * H + k]) : 0.f;
    }
    float bA = comp ? __ldg(&bsrc[ra]) : 0.f;
    float bBv = (comp && vB) ? __ldg(&bsrc[rb]) : 0.f;
    const ull biasA = half ? 0ULL : pack2(bA, bA);
    const ull biasB = half ? 0ULL : pack2(bBv, bBv);
    const float blin = __ldg(&b_lin[0]);
    const int pxor = hsel ? 0 : 1;
    const float* hbase = hsel ? hT2 : hT1;
    const int hoff = half * HOFF;
    const int growA = region * 154 + ra;
    const int growB = region * 154 + rb;

    __syncthreads();

    for (int i = 0; i <= TOT; ++i) {
        const int par = i & 1;

        // ================= DOT STAGE (2 rows per thread) =================
        if (comp) {
            const float* hp = hbase + ((par ^ pxor) * HSTRIDE) + hoff;
            ull aA[8], aB[8];
            #pragma unroll
            for (int bp = 0; bp < 8; ++bp) { aA[bp] = biasA; aB[bp] = biasB; }
            #pragma unroll
            for (int k = 0; k < KHALF; ++k) {
                const ull wdA = pack2(wA[k], wA[k]);
                const ull wdB = pack2(wB[k], wB[k]);
                const ulonglong2* qq = (const ulonglong2*)(hp + k * 16);
                ulonglong2 q0 = qq[0], q1 = qq[1], q2 = qq[2], q3 = qq[3];
                FFMA2(aA[0], wdA, q0.x); FFMA2(aA[1], wdA, q0.y);
                FFMA2(aA[2], wdA, q1.x); FFMA2(aA[3], wdA, q1.y);
                FFMA2(aA[4], wdA, q2.x); FFMA2(aA[5], wdA, q2.y);
                FFMA2(aA[6], wdA, q3.x); FFMA2(aA[7], wdA, q3.y);
                FFMA2(aB[0], wdB, q0.x); FFMA2(aB[1], wdB, q0.y);
                FFMA2(aB[2], wdB, q1.x); FFMA2(aB[3], wdB, q1.y);
                FFMA2(aB[4], wdB, q2.x); FFMA2(aB[5], wdB, q2.y);
                FFMA2(aB[6], wdB, q3.x); FFMA2(aB[7], wdB, q3.y);
            }
            #pragma unroll
            for (int bp = 0; bp < 8; ++bp) {
                ull oA = __shfl_xor_sync(pmask, aA[bp], 1);
                ull oB = __shfl_xor_sync(pmask, aB[bp], 1);
                ADDF2(aA[bp], oA);
                ADDF2(aB[bp], oB);
            }
            if (!half) {
                ull* goA = gbufU + growA * GPU;
                ull* goB = gbufU + growB * GPU;
                #pragma unroll
                for (int bp = 0; bp < 8; ++bp) { goA[bp] = aA[bp]; goB[bp] = aB[bp]; }
            }
        } else {
            int j = tid - NDOT;
            if (j < BB) {
                if (i >= 2) out[(size_t)(gb0 + j) * TOT + (i - 2)] = oacc[((i - 1) & 1) * BB + j] + blin;
                oacc[par * BB + j] = 0.f;
                if (i < T) xbuf[j] = __ldg(&input[(size_t)(gb0 + j) * T + i]);
            }
        }
        __syncthreads();

        // ================= POINTWISE STAGE =================
        float* oa  = oacc + par * BB;
        float* h2c = hT2 + par * HSTRIDE;          // h2[i-2]
        float* h2n = hT2 + (par ^ 1) * HSTRIDE;    // h2[i-1]
        float* h1c = hT1 + (par ^ 1) * HSTRIDE;    // h1[i-1]
        float* h1n = hT1 + par * HSTRIDE;          // h1[i]

        if (i < T) {
            for (int j = tid; j < 2 * NPW; j += NTHREADS) {
                if (j < NPW) {
                    if (i > 0) {
                        int u = j >> 4, b = j & 15;
                        int hx = hidx(u) + b;
                        float dir = gbufF[(GR3 + u) * GPF + b];
                        float diz = gbufF[(GR3 + 51 + u) * GPF + b];
                        float din = gbufF[(GR3 + 102 + u) * GPF + b];
                        float d2r = gbufF[(GR2 + u) * GPF + b];
                        float d2z = gbufF[(GR2 + 51 + u) * GPF + b];
                        float d2n = gbufF[(GR2 + 102 + u) * GPF + b];
                        float r = sigf(dir + d2r);
                        float z = sigf(diz + d2z);
                        float n = tanh_f(fmaf(r, d2n, din));
                        float hold = h2c[hx];
                        float hnew = n + z * (hold - n);
                        h2n[hx] = hnew;
                        atomicAdd(&oa[b], tabs[6 * H + u] * hnew);
                    }
                } else {
                    int jj = j - NPW;
                    int u = jj >> 4, b = jj & 15;
                    int hx = hidx(u) + b;
                    float x = xbuf[b];
                    float ar = gbufF[u * GPF + b];
                    float az = gbufF[(51 + u) * GPF + b];
                    float an = gbufF[(102 + u) * GPF + b];
                    float r = sigf(fmaf(x, tabs[u], tabs[3 * H + u]) + ar);
                    float z = sigf(fmaf(x, tabs[H + u], tabs[4 * H + u]) + az);
                    float n = tanh_f(fmaf(x, tabs[2 * H + u], tabs[5 * H + u]) + r * an);
                    float hold = h1c[hx];
                    h1n[hx] = n + z * (hold - n);
                }
            }
            __syncthreads();
        } else {
            for (int j = tid; j < NPW; j += NTHREADS) {
                int u = j >> 4, b = j & 15;
                int hx = hidx(u) + b;
                float dir = gbufF[(GR3 + u) * GPF + b];
                float diz = gbufF[(GR3 + 51 + u) * GPF + b];
                float din = gbufF[(GR3 + 102 + u) * GPF + b];
                float d2r = gbufF[(GR2 + u) * GPF + b];
                float d2z = gbufF[(GR2 + 51 + u) * GPF + b];
                float d2n = gbufF[(GR2 + 102 + u) * GPF + b];
                float r = sigf(dir + d2r);
                float z = sigf(diz + d2z);
                float n = tanh_f(fmaf(r, d2n, din));
                float hold = h2c[hx];
                float hnew = n + z * (hold - n);
                h2n[hx] = hnew;
                atomicAdd(&oa[b], tabs[6 * H + u] * hnew);
            }
            __syncthreads();
            for (int j = tid; j < NPW; j += NTHREADS) {
                int u = j >> 4, b = j & 15;
                int hx = hidx(u) + b;
                float x = oa[b] + blin;
                float ar = gbufF[u * GPF + b];
                float az = gbufF[(51 + u) * GPF + b];
                float an = gbufF[(102 + u) * GPF + b];
                float r = sigf(fmaf(x, tabs[u], tabs[3 * H + u]) + ar);
                float z = sigf(fmaf(x, tabs[H + u], tabs[4 * H + u]) + az);
                float n = tanh_f(fmaf(x, tabs[2 * H + u], tabs[5 * H + u]) + r * an);
                float hold = h1c[hx];
                h1n[hx] = n + z * (hold - n);
            }
            __syncthreads();
        }
    }

    if (tid < BB)
        out[(size_t)(gb0 + tid) * TOT + (TOT - 1)] = oacc[(TOT & 1) * BB + tid] + blin;
}

extern "C" void kernel_launch(void* const* d_in, const int* in_sizes, int n_in,
                              void* d_out, int out_size) {
    const float* input = (const float*)d_in[0];
    const float* w_ih1 = (const float*)d_in[2];
    const float* w_hh1 = (const float*)d_in[3];
    const float* b_ih1 = (const float*)d_in[4];
    const float* b_hh1 = (const float*)d_in[5];
    const float* w_ih2 = (const float*)d_in[6];
    const float* w_hh2 = (const float*)d_in[7];
    const float* b_ih2 = (const float*)d_in[8];
    const float* b_hh2 = (const float*)d_in[9];
    const float* w_lin = (const float*)d_in[10];
    const float* b_lin = (const float*)d_in[11];

    const int B   = 2048;
    const int T   = in_sizes[0] / B;
    const int TOT = out_size / B;
    const int F   = TOT - T;

    size_t smem = (size_t)(4 * HSTRIDE * 4 + GROWS * GPU * 8 + (7 * H + BB + 2 * BB) * 4);
    cudaFuncSetAttribute(gru2_kernel, cudaFuncAttributeMaxDynamicSharedMemorySize, (int)smem);

    gru2_kernel<<<B / BB, NTHREADS, smem>>>(
        input, w_ih1, w_hh1, b_ih1, b_hh1,
        w_ih2, w_hh2, b_ih2, b_hh2,
        w_lin, b_lin, (float*)d_out, T, F);
}